// round 16
// baseline (speedup 1.0000x reference)
#include <cuda_runtime.h>
#include <math_constants.h>

// Shapes (fixed by problem)
#define B 32
#define T 512
#define D 512
#define H 8
#define S 196
#define S4 49      // S / 4 (float4 per row)
#define LAYER_ID 2
#define K_TOP 51   // int(0.1 * 512)
#define NBLK 16    // blocks per batch
#define CHUNK 32   // t's per block

// Scratch (allocation-free rule: __device__ globals; zero-initialized)
__device__ float g_w[B * T];
__device__ float g_total[B][S];
__device__ int   g_sync[B];

// ---------------------------------------------------------------------------
// Kernel 1: cosine weights (validated R6/R9) + zeroing of g_total for this
// replay (stream order guarantees it completes before k_fused's atomics).
// ---------------------------------------------------------------------------
__global__ __launch_bounds__(256) void k_weights(
    const float* __restrict__ fore,     // (B, D)
    const float* __restrict__ embed,    // (B, T, D)
    const int*   __restrict__ targets)  // (B, T+1) int32
{
    const int b    = blockIdx.y;
    const int lane = threadIdx.x & 31;
    const int warp = threadIdx.x >> 5;
    const int t0   = (blockIdx.x * 8 + warp) * 2;

    if (blockIdx.x == 0) {
        for (int i = threadIdx.x; i < S; i += 256) g_total[b][i] = 0.f;
    }

    const float4* yrow = reinterpret_cast<const float4*>(fore + (size_t)b * D);
    const float4* x0   = reinterpret_cast<const float4*>(embed + ((size_t)b * T + t0) * D);
    const float4* x1   = x0 + D / 4;

    float4 yv[4], xa[4], xb[4];
#pragma unroll
    for (int i = 0; i < 4; i++) {
        yv[i] = __ldg(&yrow[lane + i * 32]);
        xa[i] = __ldg(&x0[lane + i * 32]);
        xb[i] = __ldg(&x1[lane + i * 32]);
    }

    float n0 = 0.f, n1 = 0.f, xs0 = 0.f, xs1 = 0.f, ys = 0.f;
#pragma unroll
    for (int i = 0; i < 4; i++) {
        float4 y = yv[i], a = xa[i], c = xb[i];
        ys  += y.x * y.x + y.y * y.y + y.z * y.z + y.w * y.w;
        n0  += a.x * y.x + a.y * y.y + a.z * y.z + a.w * y.w;
        xs0 += a.x * a.x + a.y * a.y + a.z * a.z + a.w * a.w;
        n1  += c.x * y.x + c.y * y.y + c.z * y.z + c.w * y.w;
        xs1 += c.x * c.x + c.y * c.y + c.z * c.z + c.w * c.w;
    }
#pragma unroll
    for (int o = 16; o; o >>= 1) {
        n0  += __shfl_xor_sync(0xffffffffu, n0,  o);
        n1  += __shfl_xor_sync(0xffffffffu, n1,  o);
        xs0 += __shfl_xor_sync(0xffffffffu, xs0, o);
        xs1 += __shfl_xor_sync(0xffffffffu, xs1, o);
        ys  += __shfl_xor_sync(0xffffffffu, ys,  o);
    }
    if (lane < 2) {
        const int t = t0 + lane;
        float num = lane ? n1 : n0;
        float xn2 = lane ? xs1 : xs0;
        float xn  = fmaxf(sqrtf(xn2), 1e-8f);
        float yn  = fmaxf(sqrtf(ys),  1e-8f);
        float w   = num / (xn * yn);
        int tv    = targets[b * (T + 1) + t];
        bool msk  = (t == 0) || (tv > 0);
        g_w[b * T + t] = msk ? w : -1.0f;
    }
}

// ---------------------------------------------------------------------------
// Kernel 2 (fused): grid (NBLK, B), 512 threads. Rank/select identical to
// R14. Gather VECTORIZED over s: thread = (row-slot i 0..7, s4 0..48),
// 8 heads x LDG.128 per row (128 B in flight per thread, one wave), REDG
// accumulate into g_total; last-arriving block per b normalizes.
// ---------------------------------------------------------------------------
__global__ __launch_bounds__(512) void k_fused(
    const int*   __restrict__ targets,  // (B, T+1) int32
    const float* __restrict__ attns,    // (L, B, H, T, S)
    float*       __restrict__ out)      // (B, S)
{
    __shared__ unsigned keys[T];             // 2 KB (mapped uint32)
    __shared__ float    wvals[T];            // 2 KB (raw weights)
    __shared__ int      rank[CHUNK];
    __shared__ int      sl[CHUNK];
    __shared__ float    slw[CHUNK];
    __shared__ int      s_last;
    __shared__ float    wmin[8], wmax[8];
    __shared__ float    s_mn, s_mx;

    const int c    = blockIdx.x;   // 0..NBLK-1
    const int b    = blockIdx.y;
    const int tid  = threadIdx.x;  // 0..511
    const int lane = tid & 31;
    const int warp = tid >> 5;

    // ---- Phase 1: keys + m  (identical to R14)
    if (tid < CHUNK) rank[tid] = 0;
    float w = g_w[b * T + tid];
    unsigned uf = __float_as_uint(w);
    uf = (uf & 0x80000000u) ? ~uf : (uf | 0x80000000u);   // order-preserving
    keys[tid]  = uf;
    wvals[tid] = w;

    int tv  = targets[b * (T + 1) + tid];
    int cnt = __syncthreads_count((tid == 0) || (tv > 0));
    int m   = (int)ceilf((float)cnt * 0.1f);
    m = m < K_TOP ? m : K_TOP;

    // ---- Phase 2: chunk-local rank (identical to R14)
    {
        const int myt = c * CHUNK + lane;
        const unsigned mk = keys[myt];
        const uint4* kp = reinterpret_cast<const uint4*>(keys + warp * 32);
        int r = 0;
#pragma unroll
        for (int i = 0; i < 8; i++) {
            uint4 kv = kp[i];
            const int gb = warp * 32 + i * 4;
            r += (kv.x > mk) || ((kv.x == mk) && (gb + 0 < myt));
            r += (kv.y > mk) || ((kv.y == mk) && (gb + 1 < myt));
            r += (kv.z > mk) || ((kv.z == mk) && (gb + 2 < myt));
            r += (kv.w > mk) || ((kv.w == mk) && (gb + 3 < myt));
        }
        atomicAdd(&rank[lane], r);     // 32 spread addrs per warp
    }
    __syncthreads();

    // ---- Phase 3: selected list for this chunk (identical to R14)
    bool selme = (tid < CHUNK) && (rank[tid] < m);
    if (selme) {
        int pos = 0;
#pragma unroll
        for (int i = 0; i < CHUNK; i++) pos += (i < tid) && (rank[i] < m);
        sl[pos]  = tid;
        slw[pos] = wvals[c * CHUNK + tid];
    }
    int ns = __syncthreads_count(selme);

    // ---- Phase 4: VECTORIZED gather. thread = (row-slot i, s4).
    // Per row: 8 independent LDG.128 (one per head) -> 128 B in flight.
    const int i_slot = tid / S4;       // 0..7 active (tid < 392), else idle
    const int s4     = tid - i_slot * S4;
    if (i_slot < 8 && i_slot < ns) {
        const float* abase = attns + ((size_t)(LAYER_ID * B + b)) * H * T * S;
        float4 acc = make_float4(0.f, 0.f, 0.f, 0.f);
        for (int k = i_slot; k < ns; k += 8) {
            const int   tt = c * CHUNK + sl[k];
            const float wv = slw[k];
            const float* rowb = abase + (size_t)tt * S;
            float4 v[8];
#pragma unroll
            for (int h = 0; h < H; h++)
                v[h] = __ldg(reinterpret_cast<const float4*>(rowb + (size_t)h * T * S) + s4);
            float4 hs;
            hs.x = v[0].x + v[1].x + v[2].x + v[3].x + v[4].x + v[5].x + v[6].x + v[7].x;
            hs.y = v[0].y + v[1].y + v[2].y + v[3].y + v[4].y + v[5].y + v[6].y + v[7].y;
            hs.z = v[0].z + v[1].z + v[2].z + v[3].z + v[4].z + v[5].z + v[6].z + v[7].z;
            hs.w = v[0].w + v[1].w + v[2].w + v[3].w + v[4].w + v[5].w + v[6].w + v[7].w;
            acc.x += fmaxf(wv * (hs.x * 0.125f), 0.f);
            acc.y += fmaxf(wv * (hs.y * 0.125f), 0.f);
            acc.z += fmaxf(wv * (hs.z * 0.125f), 0.f);
            acc.w += fmaxf(wv * (hs.w * 0.125f), 0.f);
        }
        float* dst = &g_total[b][s4 * 4];
        atomicAdd(dst + 0, acc.x);
        atomicAdd(dst + 1, acc.y);
        atomicAdd(dst + 2, acc.z);
        atomicAdd(dst + 3, acc.w);
    }

    // ---- Phase 5: arrival; last block per b normalizes (tiny tail)
    __threadfence();
    __syncthreads();
    if (tid == 0) {
        int done = atomicAdd(&g_sync[b], 1);
        s_last = (done == NBLK - 1);
    }
    __syncthreads();
    if (!s_last) return;
    if (tid == 0) g_sync[b] = 0;       // reset for next graph replay
    __threadfence();                   // acquire: all adds visible

    const bool active = (tid < S);
    float acc = 0.f;
    if (active) acc = g_total[b][tid] / (float)m;

    // warp-shuffle min/max over s (256 participating threads, 2 barriers)
    if (tid < 256) {
        float mn = active ? acc :  CUDART_INF_F;
        float mx = active ? acc : -CUDART_INF_F;
#pragma unroll
        for (int o = 16; o; o >>= 1) {
            mn = fminf(mn, __shfl_xor_sync(0xffffffffu, mn, o));
            mx = fmaxf(mx, __shfl_xor_sync(0xffffffffu, mx, o));
        }
        if (lane == 0) { wmin[warp] = mn; wmax[warp] = mx; }
    }
    __syncthreads();
    if (tid < 32) {
        float mn = (tid < 8) ? wmin[tid] :  CUDART_INF_F;
        float mx = (tid < 8) ? wmax[tid] : -CUDART_INF_F;
#pragma unroll
        for (int o = 4; o; o >>= 1) {
            mn = fminf(mn, __shfl_xor_sync(0xffffffffu, mn, o));
            mx = fmaxf(mx, __shfl_xor_sync(0xffffffffu, mx, o));
        }
        if (tid == 0) { s_mn = mn; s_mx = mx; }
    }
    __syncthreads();

    if (active)
        out[b * S + tid] = (acc - s_mn) / fmaxf(s_mx - s_mn, 1e-12f);
}

// ---------------------------------------------------------------------------
extern "C" void kernel_launch(void* const* d_in, const int* in_sizes, int n_in,
                              void* d_out, int out_size)
{
    const float* fore    = (const float*)d_in[0];  // (B, D)
    const float* embed   = (const float*)d_in[1];  // (B, T, D)
    const float* attns   = (const float*)d_in[2];  // (L, B, H, T, S)
    const int*   targets = (const int*)  d_in[3];  // (B, T+1) int32
    float* out = (float*)d_out;

    k_weights<<<dim3(T / 16, B), 256>>>(fore, embed, targets);
    k_fused<<<dim3(NBLK, B), 512>>>(targets, attns, out);
}

// round 17
// speedup vs baseline: 1.2402x; 1.2402x over previous
#include <cuda_runtime.h>
#include <math_constants.h>

// Shapes (fixed by problem)
#define B 32
#define T 512
#define D 512
#define H 8
#define S 196
#define LAYER_ID 2
#define K_TOP 51   // int(0.1 * 512)
#define NBLK 8     // blocks per batch  (256 total <= 296 co-resident slots)
#define CHUNK 64   // t's per block

// Scratch (allocation-free rule: __device__ globals; zero-initialized)
__device__ float g_w[B * T];
__device__ float g_total[B][S];
__device__ int   g_warr[B];   // weights-ready arrivals per batch
__device__ int   g_sync[B];   // gather-done arrivals per batch

// ---------------------------------------------------------------------------
// Single kernel. grid (NBLK, B) = 256 blocks, 512 threads, 2 blocks/SM
// guaranteed -> all co-resident (spin-safe).
// Phase A: weights for this block's 64-t chunk (y staged in smem -> no spill).
// Per-batch rendezvous. Phase B: 32-bit-key rank (R14) -> select -> gather
// (R14 loop) -> REDG into g_total; last block per b normalizes.
// ---------------------------------------------------------------------------
__global__ __launch_bounds__(512, 2) void k_all(
    const float* __restrict__ fore,     // (B, D)
    const float* __restrict__ embed,    // (B, T, D)
    const int*   __restrict__ targets,  // (B, T+1) int32
    const float* __restrict__ attns,    // (L, B, H, T, S)
    float*       __restrict__ out)      // (B, S)
{
    __shared__ float    ysh[D];              // 2 KB staged fore row
    __shared__ unsigned keys[T];             // 2 KB
    __shared__ float    wvals[T];            // 2 KB
    __shared__ int      rank[CHUNK];
    __shared__ int      sl[CHUNK];
    __shared__ float    slw[CHUNK];
    __shared__ int      s_last;
    __shared__ float    wmin[8], wmax[8];
    __shared__ float    s_mn, s_mx;

    const int c    = blockIdx.x;   // 0..NBLK-1
    const int b    = blockIdx.y;
    const int tid  = threadIdx.x;  // 0..511
    const int lane = tid & 31;
    const int warp = tid >> 5;     // 0..15

    // ================= Phase A: weights for chunk c =================
    for (int i = tid; i < D; i += 512) ysh[i] = fore[b * D + i];
    if (c == 0) {                  // zero g_total[b] before any REDG lands
        for (int i = tid; i < S; i += 512) g_total[b][i] = 0.f;
    }
    __syncthreads();

    // |y|^2 once per warp from smem
    float ys = 0.f;
    {
        const float4* y4 = reinterpret_cast<const float4*>(ysh);
#pragma unroll
        for (int i = 0; i < 4; i++) {
            float4 y = y4[lane + i * 32];
            ys += y.x * y.x + y.y * y.y + y.z * y.z + y.w * y.w;
        }
#pragma unroll
        for (int o = 16; o; o >>= 1) ys += __shfl_xor_sync(0xffffffffu, ys, o);
    }
    const float yn = fmaxf(sqrtf(ys), 1e-8f);

#pragma unroll
    for (int pass = 0; pass < 2; pass++) {     // 2 passes x 2 rows = 4 rows/warp
        const int t0 = c * CHUNK + warp * 4 + pass * 2;
        const float4* x0 = reinterpret_cast<const float4*>(embed + ((size_t)b * T + t0) * D);
        const float4* x1 = x0 + D / 4;
        const float4* y4 = reinterpret_cast<const float4*>(ysh);
        float4 xa[4], xb[4];
#pragma unroll
        for (int i = 0; i < 4; i++) {
            xa[i] = __ldg(&x0[lane + i * 32]);
            xb[i] = __ldg(&x1[lane + i * 32]);
        }
        float n0 = 0.f, n1 = 0.f, xs0 = 0.f, xs1 = 0.f;
#pragma unroll
        for (int i = 0; i < 4; i++) {
            float4 y = y4[lane + i * 32];       // LDS, low liveness
            float4 a = xa[i], cc = xb[i];
            n0  += a.x * y.x + a.y * y.y + a.z * y.z + a.w * y.w;
            xs0 += a.x * a.x + a.y * a.y + a.z * a.z + a.w * a.w;
            n1  += cc.x * y.x + cc.y * y.y + cc.z * y.z + cc.w * y.w;
            xs1 += cc.x * cc.x + cc.y * cc.y + cc.z * cc.z + cc.w * cc.w;
        }
#pragma unroll
        for (int o = 16; o; o >>= 1) {
            n0  += __shfl_xor_sync(0xffffffffu, n0,  o);
            n1  += __shfl_xor_sync(0xffffffffu, n1,  o);
            xs0 += __shfl_xor_sync(0xffffffffu, xs0, o);
            xs1 += __shfl_xor_sync(0xffffffffu, xs1, o);
        }
        if (lane < 2) {
            const int t = t0 + lane;
            float num = lane ? n1 : n0;
            float xn2 = lane ? xs1 : xs0;
            float xn  = fmaxf(sqrtf(xn2), 1e-8f);
            float wv  = num / (xn * yn);
            int tv    = targets[b * (T + 1) + t];
            bool msk  = (t == 0) || (tv > 0);
            g_w[b * T + t] = msk ? wv : -1.0f;
        }
    }

    // ---- per-batch rendezvous: release own chunk, wait for all NBLK ----
    __threadfence();
    __syncthreads();
    if (tid == 0) {
        atomicAdd(&g_warr[b], 1);
        volatile int* va = g_warr;
        while (va[b] < NBLK) { __nanosleep(64); }
    }
    __syncthreads();
    __threadfence();   // acquire

    // ================= Phase B: keys + m (R14) =================
    if (tid < CHUNK) rank[tid] = 0;
    float w = g_w[b * T + tid];
    unsigned uf = __float_as_uint(w);
    uf = (uf & 0x80000000u) ? ~uf : (uf | 0x80000000u);   // order-preserving
    keys[tid]  = uf;
    wvals[tid] = w;

    int tv  = targets[b * (T + 1) + tid];
    int cnt = __syncthreads_count((tid == 0) || (tv > 0));
    int m   = (int)ceilf((float)cnt * 0.1f);
    m = m < K_TOP ? m : K_TOP;

    // ---- rank: tl = tid&63 owns t, piece = tid>>6 (8 x 64-key slices);
    // warp w scans slice w>>1 -> whole warp same addresses (LDS broadcast).
    {
        const int tl    = tid & (CHUNK - 1);
        const int piece = tid >> 6;
        const int myt   = c * CHUNK + tl;
        const unsigned mk = keys[myt];
        const uint4* kp = reinterpret_cast<const uint4*>(keys + piece * 64);
        int r = 0;
#pragma unroll
        for (int i = 0; i < 16; i++) {
            uint4 kv = kp[i];
            const int gb = piece * 64 + i * 4;
            r += (kv.x > mk) || ((kv.x == mk) && (gb + 0 < myt));
            r += (kv.y > mk) || ((kv.y == mk) && (gb + 1 < myt));
            r += (kv.z > mk) || ((kv.z == mk) && (gb + 2 < myt));
            r += (kv.w > mk) || ((kv.w == mk) && (gb + 3 < myt));
        }
        atomicAdd(&rank[tl], r);
    }
    __syncthreads();

    // ---- selected list for this chunk, t-order (deterministic)
    bool selme = (tid < CHUNK) && (rank[tid] < m);
    if (selme) {
        int pos = 0;
#pragma unroll
        for (int i = 0; i < CHUNK; i++) pos += (i < tid) && (rank[i] < m);
        sl[pos]  = tid;
        slw[pos] = wvals[c * CHUNK + tid];
    }
    int ns = __syncthreads_count(selme);

    // ---- gather (R14 loop) -> REDG accumulate into g_total
    const int jsub = tid / S;          // 0,1 active; tid >= 392 idle
    const int s    = tid - jsub * S;
    if (jsub < 2 && ns > 0) {
        const float* base = attns + ((size_t)(LAYER_ID * B + b)) * H * T * S + s;
        float acc = 0.f;
        for (int i = jsub; i < ns; i += 4) {   // handles i and i+2 per iter
            int i2 = i + 2;
            bool a2 = (i2 < ns);
            int   t0i = c * CHUNK + sl[i];
            int   t1i = a2 ? (c * CHUNK + sl[i2]) : t0i;
            float w0  = slw[i];
            float w1  = a2 ? slw[i2] : 0.f;
            const float* p0 = base + (size_t)t0i * S;
            const float* p1 = base + (size_t)t1i * S;
            float v0[8], v1[8];
#pragma unroll
            for (int h = 0; h < H; h++) {
                v0[h] = __ldg(p0 + (size_t)h * T * S);
                v1[h] = __ldg(p1 + (size_t)h * T * S);
            }
            float h0 = 0.f, h1 = 0.f;
#pragma unroll
            for (int h = 0; h < H; h++) { h0 += v0[h]; h1 += v1[h]; }
            acc += fmaxf(w0 * (h0 * 0.125f), 0.f);
            if (a2) acc += fmaxf(w1 * (h1 * 0.125f), 0.f);
        }
        atomicAdd(&g_total[b][s], acc);        // REDG, no return
    }

    // ---- arrival; last block per b normalizes (R14 tail)
    __threadfence();
    __syncthreads();
    if (tid == 0) {
        int done = atomicAdd(&g_sync[b], 1);
        s_last = (done == NBLK - 1);
    }
    __syncthreads();
    if (!s_last) return;
    if (tid == 0) { g_sync[b] = 0; g_warr[b] = 0; }   // reset for next replay
    __threadfence();                   // acquire: all adds visible

    const bool active = (tid < S);
    float acc = 0.f;
    if (active) acc = g_total[b][tid] / (float)m;

    if (tid < 256) {
        float mn = active ? acc :  CUDART_INF_F;
        float mx = active ? acc : -CUDART_INF_F;
#pragma unroll
        for (int o = 16; o; o >>= 1) {
            mn = fminf(mn, __shfl_xor_sync(0xffffffffu, mn, o));
            mx = fmaxf(mx, __shfl_xor_sync(0xffffffffu, mx, o));
        }
        if (lane == 0) { wmin[warp] = mn; wmax[warp] = mx; }
    }
    __syncthreads();
    if (tid < 32) {
        float mn = (tid < 8) ? wmin[tid] :  CUDART_INF_F;
        float mx = (tid < 8) ? wmax[tid] : -CUDART_INF_F;
#pragma unroll
        for (int o = 4; o; o >>= 1) {
            mn = fminf(mn, __shfl_xor_sync(0xffffffffu, mn, o));
            mx = fmaxf(mx, __shfl_xor_sync(0xffffffffu, mx, o));
        }
        if (tid == 0) { s_mn = mn; s_mx = mx; }
    }
    __syncthreads();

    if (active)
        out[b * S + tid] = (acc - s_mn) / fmaxf(s_mx - s_mn, 1e-12f);
}

// ---------------------------------------------------------------------------
extern "C" void kernel_launch(void* const* d_in, const int* in_sizes, int n_in,
                              void* d_out, int out_size)
{
    const float* fore    = (const float*)d_in[0];  // (B, D)
    const float* embed   = (const float*)d_in[1];  // (B, T, D)
    const float* attns   = (const float*)d_in[2];  // (L, B, H, T, S)
    const int*   targets = (const int*)  d_in[3];  // (B, T+1) int32
    float* out = (float*)d_out;

    k_all<<<dim3(NBLK, B), 512>>>(fore, embed, targets, attns, out);
}